// round 13
// baseline (speedup 1.0000x reference)
#include <cuda_runtime.h>
#include <cstdint>

#define BATCH 4
#define SEQ   2048
#define INF   4096
#define OUTF  4096
#define RANK  16
// SCALING = 16/16 = 1.0f (elided)

// ---- phase-1 (warp MMA) ----
#define P1_T      128                 // 4 warps
#define P1_ROWS   64                  // rows per CTA
#define P1_SPLIT  8
#define KS_TOT    (INF / 16)          // 256
#define KS_SPLIT  (KS_TOT / P1_SPLIT) // 32

#define NOT       (OUTF / 8)          // 512 o-tiles

// scratch
__device__ float    g_bx[P1_SPLIT * BATCH * SEQ * RANK];   // 4 MB fp32 partials
__device__ uint32_t g_Bc[8 * 2 * KS_TOT * 2 * 2 * 32];     // 2 MB packed B
__device__ uint32_t g_Af[8 * NOT * 128];                   // 2 MB packed A

// ---- helpers --------------------------------------------------------------
__device__ __forceinline__ uint32_t bfhi2(float f0, float f1) {
    return __byte_perm(__float_as_uint(f0), __float_as_uint(f1), 0x7632);
}
__device__ __forceinline__ uint32_t bflo2(float f0, float f1) {
    const float l0 = f0 - __uint_as_float(__float_as_uint(f0) & 0xFFFF0000u);
    const float l1 = f1 - __uint_as_float(__float_as_uint(f1) & 0xFFFF0000u);
    return __byte_perm(__float_as_uint(l0), __float_as_uint(l1), 0x7632);
}
__device__ __forceinline__ void mma16816(float* d,
    uint32_t a0, uint32_t a1, uint32_t a2, uint32_t a3,
    uint32_t b0, uint32_t b1)
{
    asm volatile(
        "mma.sync.aligned.m16n8k16.row.col.f32.bf16.bf16.f32 "
        "{%0,%1,%2,%3}, {%4,%5,%6,%7}, {%8,%9}, {%0,%1,%2,%3};"
        : "+f"(d[0]), "+f"(d[1]), "+f"(d[2]), "+f"(d[3])
        : "r"(a0), "r"(a1), "r"(a2), "r"(a3), "r"(b0), "r"(b1));
}

// ---------------------------------------------------------------------------
// K0: merged conv. First 262144 threads pack B, next 262144 pack A.
// B word: ((((a*2+h)*256 + ks)*2 + j)*2 + t)*32 + lane
//   elem: rank = t*8 + lane>>2, k = ks*16 + j*8 + (lane&3)*2 (+pair)
// A word: (a*NOT + ot)*128 + h*64 + j*32 + lane
//   elem: o = ot*8 + lane>>2, r = j*8 + (lane&3)*2 (+pair)
// ---------------------------------------------------------------------------
#define NBW (8 * KS_TOT * 2 * 2 * 32)    // 262144 B-threads
__global__ void lora_conv(const float* __restrict__ Bw,
                          const float* __restrict__ Aw)
{
    const int gidx = blockIdx.x * blockDim.x + threadIdx.x;
    if (gidx < NBW) {
        const int lane = gidx & 31;
        const int t    = (gidx >> 5) & 1;
        const int j    = (gidx >> 6) & 1;
        const int ks   = (gidx >> 7) & (KS_TOT - 1);
        const int a    = gidx >> 15;
        const int r    = t * 8 + (lane >> 2);
        const float2 f = *(const float2*)(Bw + ((size_t)a * RANK + r) * INF
                                          + ks * 16 + j * 8 + (lane & 3) * 2);
        const uint32_t off = (uint32_t)(((ks * 2 + j) * 2 + t) * 32 + lane);
        g_Bc[(uint32_t)(a * 2 + 0) * (KS_TOT * 128) + off] = bfhi2(f.x, f.y);
        g_Bc[(uint32_t)(a * 2 + 1) * (KS_TOT * 128) + off] = bflo2(f.x, f.y);
    } else {
        const int idx  = gidx - NBW;
        const int lane = idx & 31;
        const int j    = (idx >> 5) & 1;
        const int ot   = (idx >> 6) & (NOT - 1);
        const int a    = idx >> 15;
        const int o    = ot * 8 + (lane >> 2);
        const float2 f = *(const float2*)(Aw + ((size_t)a * OUTF + o) * RANK
                                          + j * 8 + (lane & 3) * 2);
        uint32_t* dst = g_Af + (uint32_t)(a * NOT + ot) * 128u;
        dst[j * 32 + lane]      = bfhi2(f.x, f.y);
        dst[64 + j * 32 + lane] = bflo2(f.x, f.y);
    }
}

// ---------------------------------------------------------------------------
// K1: phase-1 tensor MMA (split-bf16, 3 terms, 6 acc chains). [R12, ~41us]
// ---------------------------------------------------------------------------
__global__ __launch_bounds__(P1_T, 6) void lora_p1_mma(
    const float* __restrict__ x,
    const int*   __restrict__ ids)
{
    const int tid  = threadIdx.x;
    const int wid  = tid >> 5;
    const int lane = tid & 31;
    const int tig  = lane & 3;
    const int b    = blockIdx.y;
    const int sp   = blockIdx.z;
    const int aid  = ids[b];

    const int row0 = blockIdx.x * P1_ROWS + wid * 16 + (lane >> 2);
    const float* xr0 = x + ((size_t)b * SEQ + row0) * INF;
    const float* xr8 = xr0 + 8 * INF;

    const uint32_t* Bhi = g_Bc + (size_t)(aid * 2 + 0) * (KS_TOT * 128);
    const uint32_t* Blo = g_Bc + (size_t)(aid * 2 + 1) * (KS_TOT * 128);

    float c0h[4] = {0,0,0,0}, c0m[4] = {0,0,0,0}, c0l[4] = {0,0,0,0};
    float c1h[4] = {0,0,0,0}, c1m[4] = {0,0,0,0}, c1l[4] = {0,0,0,0};

    const int ks0 = sp * KS_SPLIT;
#pragma unroll 4
    for (int ks = ks0; ks < ks0 + KS_SPLIT; ++ks) {
        const int k = ks * 16 + tig * 2;
        const float2 f0 = *(const float2*)(xr0 + k);
        const float2 f1 = *(const float2*)(xr8 + k);
        const float2 f2 = *(const float2*)(xr0 + k + 8);
        const float2 f3 = *(const float2*)(xr8 + k + 8);

        const uint32_t ah0 = bfhi2(f0.x, f0.y), ah1 = bfhi2(f1.x, f1.y);
        const uint32_t ah2 = bfhi2(f2.x, f2.y), ah3 = bfhi2(f3.x, f3.y);
        const uint32_t al0 = bflo2(f0.x, f0.y), al1 = bflo2(f1.x, f1.y);
        const uint32_t al2 = bflo2(f2.x, f2.y), al3 = bflo2(f3.x, f3.y);

        const uint32_t* bp = Bhi + ks * 128 + lane;
        const uint32_t* lp = Blo + ks * 128 + lane;
        const uint32_t bh00 = bp[0],  bh01 = bp[64];
        const uint32_t bh10 = bp[32], bh11 = bp[96];
        const uint32_t bl00 = lp[0],  bl01 = lp[64];
        const uint32_t bl10 = lp[32], bl11 = lp[96];

        mma16816(c0h, ah0, ah1, ah2, ah3, bh00, bh01);
        mma16816(c1h, ah0, ah1, ah2, ah3, bh10, bh11);
        mma16816(c0m, al0, al1, al2, al3, bh00, bh01);
        mma16816(c1m, al0, al1, al2, al3, bh10, bh11);
        mma16816(c0l, ah0, ah1, ah2, ah3, bl00, bl01);
        mma16816(c1l, ah0, ah1, ah2, ah3, bl10, bl11);
    }

    float acc0[4], acc1[4];
#pragma unroll
    for (int i = 0; i < 4; ++i) {
        acc0[i] = c0h[i] + c0m[i] + c0l[i];
        acc1[i] = c1h[i] + c1m[i] + c1l[i];
    }

    float* d0 = g_bx + ((size_t)(sp * BATCH + b) * SEQ + row0) * RANK;
    float* d8 = d0 + 8 * RANK;
    *(float2*)(d0 + tig * 2)     = make_float2(acc0[0], acc0[1]);
    *(float2*)(d8 + tig * 2)     = make_float2(acc0[2], acc0[3]);
    *(float2*)(d0 + 8 + tig * 2) = make_float2(acc1[0], acc1[1]);
    *(float2*)(d8 + 8 + tig * 2) = make_float2(acc1[2], acc1[3]);
}

// ---------------------------------------------------------------------------
// K2: phase-2 tensor MMA with smem-staged coalesced stores.
// Warp = one row-tile (16 rows) x 64 o-tiles; in-warp reduce of 8 partials
// produces Bx a-frags. Per 8-o-tile chunk: MMA into c-frags -> STS to a
// private 16x68 tile -> 8 coalesced STG.128 (512B/instr).
// ---------------------------------------------------------------------------
#define BUFP 68
__global__ __launch_bounds__(256) void lora_p2_mma(
    const int* __restrict__ ids,
    float*     __restrict__ out)
{
    __shared__ float buf[8][16][BUFP];          // 34.8 KB

    const int tid  = threadIdx.x;
    const int wid  = tid >> 5;
    const int lane = tid & 31;
    const int oc   = blockIdx.x;                // 0..7 (512-col chunk)
    const int rt   = blockIdx.y * 8 + wid;      // row-tile 0..511
    const int b    = rt >> 7;
    const int nt   = rt & 127;
    const int aid  = ids[b];

    // in-warp reduce of 8 partials -> Bx a-frags (hi/lo)
    const int rown = nt * 16 + (lane >> 2);
    const int k0   = (lane & 3) * 2;
    float2 s00 = {0.f,0.f}, s10 = {0.f,0.f}, s01 = {0.f,0.f}, s11 = {0.f,0.f};
#pragma unroll
    for (int sp = 0; sp < P1_SPLIT; ++sp) {
        const float* p = g_bx + ((size_t)(sp * BATCH + b) * SEQ + rown) * RANK;
        const float* q = p + 8 * RANK;
        const float2 v00 = *(const float2*)(p + k0);
        const float2 v01 = *(const float2*)(p + k0 + 8);
        const float2 v10 = *(const float2*)(q + k0);
        const float2 v11 = *(const float2*)(q + k0 + 8);
        s00.x += v00.x; s00.y += v00.y;  s01.x += v01.x; s01.y += v01.y;
        s10.x += v10.x; s10.y += v10.y;  s11.x += v11.x; s11.y += v11.y;
    }
    const uint32_t ah0 = bfhi2(s00.x, s00.y), ah1 = bfhi2(s10.x, s10.y);
    const uint32_t ah2 = bfhi2(s01.x, s01.y), ah3 = bfhi2(s11.x, s11.y);
    const uint32_t al0 = bflo2(s00.x, s00.y), al1 = bflo2(s10.x, s10.y);
    const uint32_t al2 = bflo2(s01.x, s01.y), al3 = bflo2(s11.x, s11.y);

    const uint32_t* Ab = g_Af + (size_t)aid * (NOT * 128);
    float* outb = out + ((size_t)b * SEQ + nt * 16) * OUTF;
    const int r4 = lane >> 2;
    const int co = (lane & 3) * 2;

#pragma unroll 1
    for (int c8 = 0; c8 < 8; ++c8) {
        const int otb = oc * 64 + c8 * 8;
#pragma unroll
        for (int oti = 0; oti < 8; ++oti) {
            const uint32_t* ap = Ab + (otb + oti) * 128 + lane;
            const uint32_t bh0 = ap[0],  bh1 = ap[32];
            const uint32_t bl0 = ap[64], bl1 = ap[96];
            float c[4] = {0.f, 0.f, 0.f, 0.f};
            mma16816(c, ah0, ah1, ah2, ah3, bh0, bh1);   // hi*hi
            mma16816(c, al0, al1, al2, al3, bh0, bh1);   // lo*hi
            mma16816(c, ah0, ah1, ah2, ah3, bl0, bl1);   // hi*lo
            *(float2*)&buf[wid][r4][oti * 8 + co]     = make_float2(c[0], c[1]);
            *(float2*)&buf[wid][r4 + 8][oti * 8 + co] = make_float2(c[2], c[3]);
        }
        __syncwarp();
        const int colb = otb * 8;                // global col base
#pragma unroll
        for (int i = 0; i < 8; ++i) {
            const int row = i * 2 + (lane >> 4);
            const int f4  = lane & 15;
            *(float4*)(outb + (size_t)row * OUTF + colb + f4 * 4) =
                *(float4*)&buf[wid][row][f4 * 4];
        }
        __syncwarp();
    }
}

// ---------------------------------------------------------------------------
extern "C" void kernel_launch(void* const* d_in, const int* in_sizes, int n_in,
                              void* d_out, int out_size)
{
    const float* x   = (const float*)d_in[0];   // [4,2048,4096]
    const float* Aw  = (const float*)d_in[1];   // [8,4096,16]
    const float* Bw  = (const float*)d_in[2];   // [8,16,4096]
    const int*   ids = (const int*)  d_in[3];   // [4]
    float*       out = (float*)d_out;           // [4,2048,4096]

    lora_conv<<<(2 * NBW) / 256, 256>>>(Bw, Aw);          // 2048 CTAs

    dim3 g1(SEQ / P1_ROWS, BATCH, P1_SPLIT);              // (32,4,8) = 1024 CTAs
    lora_p1_mma<<<g1, P1_T>>>(x, ids);

    dim3 g2(8, 64);                                       // 512 CTAs
    lora_p2_mma<<<g2, 256>>>(ids, out);
}

// round 14
// speedup vs baseline: 1.1187x; 1.1187x over previous
#include <cuda_runtime.h>
#include <cstdint>

#define BATCH 4
#define SEQ   2048
#define INF   4096
#define OUTF  4096
#define RANK  16
// SCALING = 16/16 = 1.0f (elided)

// ---- phase-1 ----
#define P1_SPLIT  8
#define KS_TOT    256               // 16-wide k-steps total
#define KS_SPLIT  (KS_TOT / P1_SPLIT)   // 32 ks per split (512 k)
#define P1_CK     64                // k per staged chunk
#define P1_NCHK   8                 // chunks per split
#define XPITCH    72                // bf16 elems per smem row (144 B)

#define NOT       (OUTF / 8)        // 512 o-tiles

// scratch
__device__ float    g_bx[P1_SPLIT * BATCH * SEQ * RANK];   // 4 MB partials
__device__ uint32_t g_Bc[8 * 2 * KS_TOT * 128];            // 2 MB packed B
__device__ uint32_t g_Af[8 * NOT * 128];                   // 2 MB packed A

// ---- helpers --------------------------------------------------------------
__device__ __forceinline__ uint32_t bfhi2(float f0, float f1) {
    return __byte_perm(__float_as_uint(f0), __float_as_uint(f1), 0x7632);
}
__device__ __forceinline__ uint32_t bflo2(float f0, float f1) {
    const float l0 = f0 - __uint_as_float(__float_as_uint(f0) & 0xFFFF0000u);
    const float l1 = f1 - __uint_as_float(__float_as_uint(f1) & 0xFFFF0000u);
    return __byte_perm(__float_as_uint(l0), __float_as_uint(l1), 0x7632);
}
__device__ __forceinline__ void mma16816(float* d,
    uint32_t a0, uint32_t a1, uint32_t a2, uint32_t a3,
    uint32_t b0, uint32_t b1)
{
    asm volatile(
        "mma.sync.aligned.m16n8k16.row.col.f32.bf16.bf16.f32 "
        "{%0,%1,%2,%3}, {%4,%5,%6,%7}, {%8,%9}, {%0,%1,%2,%3};"
        : "+f"(d[0]), "+f"(d[1]), "+f"(d[2]), "+f"(d[3])
        : "r"(a0), "r"(a1), "r"(a2), "r"(a3), "r"(b0), "r"(b1));
}
__device__ __forceinline__ void ldmx4(uint32_t& r0, uint32_t& r1,
                                      uint32_t& r2, uint32_t& r3, uint32_t addr)
{
    asm volatile("ldmatrix.sync.aligned.m8n8.x4.shared.b16 {%0,%1,%2,%3}, [%4];"
                 : "=r"(r0), "=r"(r1), "=r"(r2), "=r"(r3) : "r"(addr));
}
__device__ __forceinline__ uint32_t smem_u32(const void* p) {
    return (uint32_t)__cvta_generic_to_shared(p);
}

// ---------------------------------------------------------------------------
// K0: merged conv (B-frags then A-frags). [R13, validated]
// ---------------------------------------------------------------------------
#define NBW (8 * KS_TOT * 2 * 2 * 32)    // 262144 B-threads
__global__ void lora_conv(const float* __restrict__ Bw,
                          const float* __restrict__ Aw)
{
    const int gidx = blockIdx.x * blockDim.x + threadIdx.x;
    if (gidx < NBW) {
        const int lane = gidx & 31;
        const int t    = (gidx >> 5) & 1;
        const int j    = (gidx >> 6) & 1;
        const int ks   = (gidx >> 7) & (KS_TOT - 1);
        const int a    = gidx >> 15;
        const int r    = t * 8 + (lane >> 2);
        const float2 f = *(const float2*)(Bw + ((size_t)a * RANK + r) * INF
                                          + ks * 16 + j * 8 + (lane & 3) * 2);
        const uint32_t off = (uint32_t)(((ks * 2 + j) * 2 + t) * 32 + lane);
        g_Bc[(uint32_t)(a * 2 + 0) * (KS_TOT * 128) + off] = bfhi2(f.x, f.y);
        g_Bc[(uint32_t)(a * 2 + 1) * (KS_TOT * 128) + off] = bflo2(f.x, f.y);
    } else {
        const int idx  = gidx - NBW;
        const int lane = idx & 31;
        const int j    = (idx >> 5) & 1;
        const int ot   = (idx >> 6) & (NOT - 1);
        const int a    = idx >> 15;
        const int o    = ot * 8 + (lane >> 2);
        const float2 f = *(const float2*)(Aw + ((size_t)a * OUTF + o) * RANK
                                          + j * 8 + (lane & 3) * 2);
        uint32_t* dst = g_Af + (uint32_t)(a * NOT + ot) * 128u;
        dst[j * 32 + lane]      = bfhi2(f.x, f.y);
        dst[64 + j * 32 + lane] = bflo2(f.x, f.y);
    }
}

// ---------------------------------------------------------------------------
// K1: phase-1 MMA with coalesced x staging + ldmatrix.
// CTA = 128 thr (4 warps x m16 rows = 64 rows); chunks of 64 k staged as
// split-bf16 hi/lo smem planes (pitch 144 B -> conflict-free LDSM).
// ---------------------------------------------------------------------------
__global__ __launch_bounds__(128) void lora_p1_mma(
    const float* __restrict__ x,
    const int*   __restrict__ ids)
{
    __shared__ __align__(16) uint16_t sh[64 * XPITCH];   // 9216 B... x2 planes
    __shared__ __align__(16) uint16_t sl[64 * XPITCH];

    const int tid  = threadIdx.x;
    const int wid  = tid >> 5;
    const int lane = tid & 31;
    const int b    = blockIdx.y;
    const int sp   = blockIdx.z;
    const int aid  = ids[b];
    const int rowBase = blockIdx.x * 64;

    const float* xb = x + ((size_t)b * SEQ + rowBase) * INF + sp * (KS_SPLIT * 16);
    const uint32_t* Bhi = g_Bc + (size_t)(aid * 2 + 0) * (KS_TOT * 128);
    const uint32_t* Blo = g_Bc + (size_t)(aid * 2 + 1) * (KS_TOT * 128);

    const uint32_t shb = smem_u32(sh);
    const uint32_t slb = smem_u32(sl);
    // ldmatrix lane->row map: lanes 0-7 rows 0-7 (a0), 8-15 rows 8-15 (a1),
    // 16-23 rows 0-7 col+8 (a2), 24-31 rows 8-15 col+8 (a3)
    const uint32_t lmoff = (uint32_t)(wid * 16 + (lane & 15)) * 144u
                         + (uint32_t)(lane >> 4) * 16u;

    float c0h[4] = {0,0,0,0}, c0m[4] = {0,0,0,0}, c0l[4] = {0,0,0,0};
    float c1h[4] = {0,0,0,0}, c1m[4] = {0,0,0,0}, c1l[4] = {0,0,0,0};

    float4 xr[8];
#pragma unroll
    for (int i = 0; i < 8; ++i) {
        const int idx = i * 128 + tid, row = idx >> 4, c4 = idx & 15;
        xr[i] = *(const float4*)(xb + (size_t)row * INF + c4 * 4);
    }

#pragma unroll 1
    for (int ch = 0; ch < P1_NCHK; ++ch) {
        // STS staged chunk (convert f32 -> bf16 hi/lo)
#pragma unroll
        for (int i = 0; i < 8; ++i) {
            const int idx = i * 128 + tid, row = idx >> 4, c4 = idx & 15;
            const uint32_t off = (uint32_t)row * XPITCH + (uint32_t)c4 * 4;
            *(uint32_t*)(sh + off)     = bfhi2(xr[i].x, xr[i].y);
            *(uint32_t*)(sh + off + 2) = bfhi2(xr[i].z, xr[i].w);
            *(uint32_t*)(sl + off)     = bflo2(xr[i].x, xr[i].y);
            *(uint32_t*)(sl + off + 2) = bflo2(xr[i].z, xr[i].w);
        }
        __syncthreads();
        if (ch + 1 < P1_NCHK) {
#pragma unroll
            for (int i = 0; i < 8; ++i) {
                const int idx = i * 128 + tid, row = idx >> 4, c4 = idx & 15;
                xr[i] = *(const float4*)(xb + (size_t)row * INF
                                         + (ch + 1) * P1_CK + c4 * 4);
            }
        }
#pragma unroll
        for (int ksi = 0; ksi < 4; ++ksi) {
            uint32_t ah0, ah1, ah2, ah3, al0, al1, al2, al3;
            ldmx4(ah0, ah1, ah2, ah3, shb + lmoff + ksi * 32);
            ldmx4(al0, al1, al2, al3, slb + lmoff + ksi * 32);
            const int ksg = sp * KS_SPLIT + ch * 4 + ksi;
            const uint32_t* bp = Bhi + ksg * 128 + lane;
            const uint32_t* lp = Blo + ksg * 128 + lane;
            const uint32_t bh00 = bp[0],  bh01 = bp[64];
            const uint32_t bh10 = bp[32], bh11 = bp[96];
            const uint32_t bl00 = lp[0],  bl01 = lp[64];
            const uint32_t bl10 = lp[32], bl11 = lp[96];

            mma16816(c0h, ah0, ah1, ah2, ah3, bh00, bh01);
            mma16816(c1h, ah0, ah1, ah2, ah3, bh10, bh11);
            mma16816(c0m, al0, al1, al2, al3, bh00, bh01);
            mma16816(c1m, al0, al1, al2, al3, bh10, bh11);
            mma16816(c0l, ah0, ah1, ah2, ah3, bl00, bl01);
            mma16816(c1l, ah0, ah1, ah2, ah3, bl10, bl11);
        }
        __syncthreads();
    }

    float acc0[4], acc1[4];
#pragma unroll
    for (int i = 0; i < 4; ++i) {
        acc0[i] = c0h[i] + c0m[i] + c0l[i];
        acc1[i] = c1h[i] + c1m[i] + c1l[i];
    }

    const int row0 = rowBase + wid * 16 + (lane >> 2);
    const int tig  = lane & 3;
    float* d0 = g_bx + ((size_t)(sp * BATCH + b) * SEQ + row0) * RANK;
    float* d8 = d0 + 8 * RANK;
    *(float2*)(d0 + tig * 2)     = make_float2(acc0[0], acc0[1]);
    *(float2*)(d8 + tig * 2)     = make_float2(acc0[2], acc0[3]);
    *(float2*)(d0 + 8 + tig * 2) = make_float2(acc1[0], acc1[1]);
    *(float2*)(d8 + 8 + tig * 2) = make_float2(acc1[2], acc1[3]);
}

// ---------------------------------------------------------------------------
// K2: phase-2 MMA, A-frags staged in CTA smem, 2 row-tiles per warp,
// smem-staged coalesced output stores.
// ---------------------------------------------------------------------------
#define P2_SMEM (32768 + 34816)      // A chunk + 8x16x68 store buffer
__global__ __launch_bounds__(256) void lora_p2_mma(
    const int* __restrict__ ids,
    float*     __restrict__ out)
{
    extern __shared__ __align__(16) char p2sm[];
    uint32_t* Asm = (uint32_t*)p2sm;                 // 8192 words (32 KB)
    float*    buf = (float*)(p2sm + 32768);          // [8 warps][16][68]

    const int tid  = threadIdx.x;
    const int wid  = tid >> 5;
    const int lane = tid & 31;
    const int oc   = blockIdx.x;                     // 0..7 (512-col chunk)
    const int g    = blockIdx.y;                     // 0..31
    const int rt0  = g * 16 + wid * 2;               // this warp's row-tiles
    const int b    = rt0 >> 7;
    const int aid  = ids[b];

    // stage A chunk for this oc (coalesced)
    {
        const uint4* src = (const uint4*)(g_Af + (size_t)aid * (NOT * 128) + oc * 8192);
        uint4* dst = (uint4*)Asm;
#pragma unroll
        for (int i = 0; i < 8; ++i) dst[i * 256 + tid] = src[i * 256 + tid];
    }
    __syncthreads();

    // reduce 8 partials -> a-frags (hi/lo) for both row-tiles
    uint32_t ah[2][4], al[2][4];
#pragma unroll
    for (int r = 0; r < 2; ++r) {
        const int nt   = (rt0 + r) & 127;
        const int rown = nt * 16 + (lane >> 2);
        const int k0   = (lane & 3) * 2;
        float2 s00 = {0,0}, s10 = {0,0}, s01 = {0,0}, s11 = {0,0};
#pragma unroll
        for (int sp = 0; sp < P1_SPLIT; ++sp) {
            const float* p = g_bx + ((size_t)(sp * BATCH + b) * SEQ + rown) * RANK;
            const float* q = p + 8 * RANK;
            const float2 v00 = *(const float2*)(p + k0);
            const float2 v01 = *(const float2*)(p + k0 + 8);
            const float2 v10 = *(const float2*)(q + k0);
            const float2 v11 = *(const float2*)(q + k0 + 8);
            s00.x += v00.x; s00.y += v00.y;  s01.x += v01.x; s01.y += v01.y;
            s10.x += v10.x; s10.y += v10.y;  s11.x += v11.x; s11.y += v11.y;
        }
        ah[r][0] = bfhi2(s00.x, s00.y); ah[r][1] = bfhi2(s10.x, s10.y);
        ah[r][2] = bfhi2(s01.x, s01.y); ah[r][3] = bfhi2(s11.x, s11.y);
        al[r][0] = bflo2(s00.x, s00.y); al[r][1] = bflo2(s10.x, s10.y);
        al[r][2] = bflo2(s01.x, s01.y); al[r][3] = bflo2(s11.x, s11.y);
    }

    float* outb0 = out + ((size_t)b * SEQ + (rt0 & 127) * 16) * OUTF;
    float* mybuf = buf + wid * (16 * 68);
    const int r4 = lane >> 2;
    const int co = (lane & 3) * 2;

#pragma unroll 1
    for (int c8 = 0; c8 < 8; ++c8) {
        const int colb = oc * 512 + c8 * 64;
#pragma unroll
        for (int r = 0; r < 2; ++r) {
#pragma unroll
            for (int oti = 0; oti < 8; ++oti) {
                const uint32_t* ap = Asm + (c8 * 8 + oti) * 128 + lane;
                const uint32_t bh0 = ap[0],  bh1 = ap[32];
                const uint32_t bl0 = ap[64], bl1 = ap[96];
                float c[4] = {0.f, 0.f, 0.f, 0.f};
                mma16816(c, ah[r][0], ah[r][1], ah[r][2], ah[r][3], bh0, bh1);
                mma16816(c, al[r][0], al[r][1], al[r][2], al[r][3], bh0, bh1);
                mma16816(c, ah[r][0], ah[r][1], ah[r][2], ah[r][3], bl0, bl1);
                *(float2*)&mybuf[r4 * 68 + oti * 8 + co]       = make_float2(c[0], c[1]);
                *(float2*)&mybuf[(r4 + 8) * 68 + oti * 8 + co] = make_float2(c[2], c[3]);
            }
            __syncwarp();
            float* ob = outb0 + (size_t)r * 16 * OUTF;
#pragma unroll
            for (int i = 0; i < 8; ++i) {
                const int row = i * 2 + (lane >> 4);
                const int f4  = lane & 15;
                *(float4*)(ob + (size_t)row * OUTF + colb + f4 * 4) =
                    *(float4*)&mybuf[row * 68 + f4 * 4];
            }
            __syncwarp();
        }
    }
}

// ---------------------------------------------------------------------------
extern "C" void kernel_launch(void* const* d_in, const int* in_sizes, int n_in,
                              void* d_out, int out_size)
{
    const float* x   = (const float*)d_in[0];   // [4,2048,4096]
    const float* Aw  = (const float*)d_in[1];   // [8,4096,16]
    const float* Bw  = (const float*)d_in[2];   // [8,16,4096]
    const int*   ids = (const int*)  d_in[3];   // [4]
    float*       out = (float*)d_out;           // [4,2048,4096]

    cudaFuncSetAttribute(lora_p2_mma,
                         cudaFuncAttributeMaxDynamicSharedMemorySize, P2_SMEM);

    lora_conv<<<(2 * NBW) / 256, 256>>>(Bw, Aw);          // 2048 CTAs

    dim3 g1(SEQ / 64, BATCH, P1_SPLIT);                   // (32,4,8) = 1024 CTAs
    lora_p1_mma<<<g1, 128>>>(x, ids);

    dim3 g2(8, 32);                                       // 256 CTAs
    lora_p2_mma<<<g2, 256, P2_SMEM>>>(ids, out);
}